// round 14
// baseline (speedup 1.0000x reference)
#include <cuda_runtime.h>
#include <cuda_fp16.h>
#include <cstdint>

#define XN 32
#define CIN 256
#define HIN 56
#define WIN 56
#define S_IN 3136
#define COUT 256
#define HOUT 28
#define WOUT 28
#define S_OUT 784
#define M_TOTAL 25088
#define X_ELEMS (XN * CIN * S_IN)

// Device scratch (no cudaMalloc allowed)
__device__ __align__(16) __half g_xh[(size_t)XN * S_IN * CIN];   // 51.4 MB NHWC fp16
__device__ __align__(16) __half g_wh[(size_t)COUT * 9 * CIN];    // [co][tap][ci] fp16

// ---------------------------------------------------------------------------
// Kernel 1: quantize x (round-half-even, clamp [-128,127]) as fp16 +
// NCHW -> N(S)C transpose via smem tile (128 ch x 32 spatial), float2 loads.
// Block column bx==98 quantizes the weights (merged; proven).
// ---------------------------------------------------------------------------
__global__ void quant_kernel(const float* __restrict__ x,
                             const float* __restrict__ w) {
    __shared__ __align__(16) __half tile[32 * 130];  // pitch 130 -> conflict-free
    const int t = threadIdx.x;

    if (blockIdx.x == 98) {
        // ---- weights: OIHW fp32 (int-valued) -> [co][tap][ci] fp16 ----
        const int wblock = blockIdx.y * 32 + blockIdx.z;   // 0..63
#pragma unroll 4
        for (int j = 0; j < 36; ++j) {
            int idx = wblock * 9216 + j * 256 + t;
            int co  = idx / (9 * CIN);
            int r   = idx - co * 9 * CIN;
            int tap = r >> 8;
            int ci  = r & 255;
            g_wh[idx] = __int2half_rn(
                __float2int_rn(w[(size_t)co * CIN * 9 + (size_t)ci * 9 + tap]));
        }
        return;
    }

    const int n  = blockIdx.z;
    const int c0 = blockIdx.y * 128;
    const int s0 = blockIdx.x * 32;

    const float* xb = x + (size_t)n * CIN * S_IN;
#pragma unroll
    for (int it = 0; it < 8; ++it) {
        int i   = it * 256 + t;          // 0..2047
        int cl  = i >> 4;                // 0..127
        int sl2 = (i & 15) * 2;          // 0,2,..,30
        float2 v = *(const float2*)&xb[(size_t)(c0 + cl) * S_IN + (s0 + sl2)];
        int q0 = __float2int_rn(v.x * 20.0f);   // round-half-even == jnp.round
        int q1 = __float2int_rn(v.y * 20.0f);
        q0 = max(-128, min(127, q0));
        q1 = max(-128, min(127, q1));
        tile[sl2 * 130 + cl]       = __int2half_rn(q0);   // exact (|q|<=128)
        tile[(sl2 + 1) * 130 + cl] = __int2half_rn(q1);
    }
    __syncthreads();

    __half* ob = g_xh + ((size_t)n * S_IN + s0) * CIN + c0;
#pragma unroll
    for (int it = 0; it < 8; ++it) {
        int u  = it * 256 + t;
        int sl = u >> 6;   // 0..31
        int cu = u & 63;   // channel pairs
        uint32_t val = *(const uint32_t*)&tile[sl * 130 + cu * 2];
        *(uint32_t*)&ob[(size_t)sl * CIN + cu * 2] = val;
    }
}

// ---------------------------------------------------------------------------
// Kernel 2: implicit GEMM conv, fp16 mma.sync m16n8k16 — R13-proven body.
// ONLY delta: __launch_bounds__(256, 3) -> 85 regs/thread, occupancy 3.
//  * 24 warps/SM (was 16): +50% latency hiding vs the LDSM->MMA chains
//  * grid 392 <= 148*3 = 444: the ENTIRE grid runs in one wave (was 1.32)
// Smem: 3 CTAs x 73728 = 221KB <= 227KB. ptxas spills cold loader/epilogue
// state (touched 1x/chunk), not the hot acc regs (32x/chunk).
// ---------------------------------------------------------------------------
#define PITCH 144
#define TILEB (128 * PITCH)          // 18432 per A or B tile
#define STGB  (2 * TILEB)            // 36864 per stage
#define SMEMT (2 * STGB)             // 73728 (2 stages)

__device__ __forceinline__ void cp16(uint32_t dst, const void* src, int sz) {
    asm volatile("cp.async.cg.shared.global [%0], [%1], 16, %2;\n"
                 :: "r"(dst), "l"(src), "r"(sz));
}
#define LDSM4(r0, r1, r2, r3, addr)                                          \
    asm volatile("ldmatrix.sync.aligned.m8n8.x4.shared.b16 {%0,%1,%2,%3}, [%4];" \
                 : "=r"(r0), "=r"(r1), "=r"(r2), "=r"(r3) : "r"(addr))
#define MMAF16(d, a, b0_, b1_)                                                \
    asm volatile(                                                             \
        "mma.sync.aligned.m16n8k16.row.col.f32.f16.f16.f32 "                 \
        "{%0,%1,%2,%3}, {%4,%5,%6,%7}, {%8,%9}, {%0,%1,%2,%3};\n"            \
        : "+f"(d[0]), "+f"(d[1]), "+f"(d[2]), "+f"(d[3])                     \
        : "r"(a[0]), "r"(a[1]), "r"(a[2]), "r"(a[3]), "r"(b0_), "r"(b1_))

__global__ void __launch_bounds__(256, 3) conv_mma_kernel(float* __restrict__ out) {
    extern __shared__ char dsm[];
    const uint32_t sbase = (uint32_t)__cvta_generic_to_shared(dsm);

    const int t      = threadIdx.x;
    const int lane   = t & 31;
    const int warp_m = (t >> 5) & 3;   // 0..3
    const int warp_n = t >> 7;         // 0..1
    const int m0     = blockIdx.x * 128;
    const int co0    = blockIdx.y * 128;

    // Loader: thread t -> row t/2 (0..127), 64B half t%2 (4 x 16B segments)
    const int lrow  = t >> 1;
    const int lhalf = t & 1;

    int m   = m0 + lrow;
    int n   = m / S_OUT;
    int rem = m - n * S_OUT;
    int ho  = rem / WOUT;
    int wo  = rem - ho * WOUT;
    const int hb = 2 * ho - 1;
    const int wb = 2 * wo - 1;
    const __half* an = g_xh + (size_t)n * S_IN * CIN + lhalf * 32;
    const __half* bw = g_wh + (size_t)(co0 + lrow) * 9 * CIN + lhalf * 32;

    const uint32_t dstA = sbase + (uint32_t)(lrow * PITCH + lhalf * 64);
    const uint32_t dstB = dstA + TILEB;

    // ldmatrix lane offsets (proven fragment maps)
    const uint32_t a_lane = (uint32_t)((lane & 15) * PITCH + (lane >> 4) * 16);
    const uint32_t b_lane = (uint32_t)(((lane & 7) + ((lane >> 4) << 3)) * PITCH +
                                       (((lane >> 3) & 1) << 4));
    const uint32_t aBase0 = sbase + (warp_m * 32) * PITCH + a_lane;
    const uint32_t bBase0 = sbase + TILEB + (warp_n * 64) * PITCH + b_lane;

    float acc[2][8][4];
#pragma unroll
    for (int mi = 0; mi < 2; ++mi)
#pragma unroll
        for (int ni = 0; ni < 8; ++ni)
#pragma unroll
            for (int k = 0; k < 4; ++k) acc[mi][ni][k] = 0.0f;

    auto issue = [&](int c, int st) {
        int tap = c >> 2;
        int kc  = (c & 3) * 64;
        int kh  = tap / 3;
        int kw  = tap - kh * 3;
        int hi  = hb + kh, wi = wb + kw;
        bool v  = ((unsigned)hi < (unsigned)HIN) && ((unsigned)wi < (unsigned)WIN);
        const __half* asrc = an + ((size_t)(hi * WIN + wi) * CIN + kc);
        const __half* bsrc = bw + (tap * CIN + kc);
        uint32_t so = (uint32_t)(st * STGB);
#pragma unroll
        for (int i = 0; i < 4; ++i) {
            cp16(dstA + so + i * 16, v ? (const void*)(asrc + i * 8) : (const void*)g_xh,
                 v ? 16 : 0);
            cp16(dstB + so + i * 16, bsrc + i * 8, 16);
        }
    };

    issue(0, 0);
    asm volatile("cp.async.commit_group;\n" ::: "memory");

#pragma unroll 1
    for (int c = 0; c < 36; ++c) {
        if (c < 35) {
            issue(c + 1, (c + 1) & 1);
            asm volatile("cp.async.commit_group;\n" ::: "memory");
            asm volatile("cp.async.wait_group 1;\n" ::: "memory");
        } else {
            asm volatile("cp.async.wait_group 0;\n" ::: "memory");
        }
        __syncthreads();

        const uint32_t so = (uint32_t)((c & 1) * STGB);
        const uint32_t aB = aBase0 + so;
        const uint32_t bB = bBase0 + so;
#pragma unroll
        for (int ks = 0; ks < 4; ++ks) {
            const uint32_t kb = ks * 32;   // 16 fp16 per k-step
            uint32_t a[2][4];
            LDSM4(a[0][0], a[0][1], a[0][2], a[0][3], aB + kb);
            LDSM4(a[1][0], a[1][1], a[1][2], a[1][3], aB + 16 * PITCH + kb);
#pragma unroll
            for (int p = 0; p < 4; ++p) {
                uint32_t b0, b1, b2, b3;
                LDSM4(b0, b1, b2, b3, bB + p * (16 * PITCH) + kb);
#pragma unroll
                for (int mi = 0; mi < 2; ++mi) {
                    MMAF16(acc[mi][2 * p],     a[mi], b0, b1);
                    MMAF16(acc[mi][2 * p + 1], a[mi], b2, b3);
                }
            }
        }
        __syncthreads();
    }

    // Epilogue: dequantize and store NCHW fp32 (acc are exact integers).
    const float sc = (float)(0.05 * 0.01);
#pragma unroll
    for (int mi = 0; mi < 2; ++mi) {
#pragma unroll
        for (int rr = 0; rr < 2; ++rr) {
            int mm = m0 + warp_m * 32 + mi * 16 + (lane >> 2) + rr * 8;
            int nn = mm / S_OUT;
            int ss = mm - nn * S_OUT;
            float* op = out + (size_t)nn * COUT * S_OUT + ss;
#pragma unroll
            for (int ni = 0; ni < 8; ++ni) {
                int co = co0 + warp_n * 64 + ni * 8 + (lane & 3) * 2;
                op[(size_t)co * S_OUT]       = acc[mi][ni][rr * 2 + 0] * sc;
                op[(size_t)(co + 1) * S_OUT] = acc[mi][ni][rr * 2 + 1] * sc;
            }
        }
    }
}

// ---------------------------------------------------------------------------
extern "C" void kernel_launch(void* const* d_in, const int* in_sizes, int n_in,
                              void* d_out, int out_size) {
    const float* x = (const float*)d_in[0];
    const float* w = (const float*)d_in[1];
    if (n_in >= 2 && in_sizes[0] != X_ELEMS) {
        const float* tmp = x; x = w; w = tmp;
    }
    float* out = (float*)d_out;

    dim3 g1(99, 2, 32);   // bx<98: activations; bx==98: weights (64 sub-blocks)
    quant_kernel<<<g1, 256>>>(x, w);

    cudaFuncSetAttribute(conv_mma_kernel,
                         cudaFuncAttributeMaxDynamicSharedMemorySize, SMEMT);
    dim3 g3(M_TOTAL / 128, COUT / 128);  // (196, 2)
    conv_mma_kernel<<<g3, 256, SMEMT>>>(out);
}

// round 15
// speedup vs baseline: 1.1087x; 1.1087x over previous
#include <cuda_runtime.h>
#include <cuda_fp16.h>
#include <cstdint>

#define XN 32
#define CIN 256
#define HIN 56
#define WIN 56
#define S_IN 3136
#define COUT 256
#define HOUT 28
#define WOUT 28
#define S_OUT 784
#define M_TOTAL 25088
#define X_ELEMS (XN * CIN * S_IN)

// Device scratch (no cudaMalloc allowed)
__device__ __align__(16) __half g_xh[(size_t)XN * S_IN * CIN];   // 51.4 MB NHWC fp16
__device__ __align__(16) __half g_wh[(size_t)COUT * 9 * CIN];    // [co][tap][ci] fp16

// ---------------------------------------------------------------------------
// Kernel 1: quantize x (round-half-even, clamp [-128,127]) as fp16 +
// NCHW -> N(S)C transpose via smem tile (128 ch x 32 spatial), float2 loads.
// Block column bx==98 quantizes the weights (merged; proven).
// ---------------------------------------------------------------------------
__global__ void quant_kernel(const float* __restrict__ x,
                             const float* __restrict__ w) {
    __shared__ __align__(16) __half tile[32 * 130];  // pitch 130 -> conflict-free
    const int t = threadIdx.x;

    if (blockIdx.x == 98) {
        // ---- weights: OIHW fp32 (int-valued) -> [co][tap][ci] fp16 ----
        const int wblock = blockIdx.y * 32 + blockIdx.z;   // 0..63
#pragma unroll 4
        for (int j = 0; j < 36; ++j) {
            int idx = wblock * 9216 + j * 256 + t;
            int co  = idx / (9 * CIN);
            int r   = idx - co * 9 * CIN;
            int tap = r >> 8;
            int ci  = r & 255;
            g_wh[idx] = __int2half_rn(
                __float2int_rn(w[(size_t)co * CIN * 9 + (size_t)ci * 9 + tap]));
        }
        return;
    }

    const int n  = blockIdx.z;
    const int c0 = blockIdx.y * 128;
    const int s0 = blockIdx.x * 32;

    const float* xb = x + (size_t)n * CIN * S_IN;
#pragma unroll
    for (int it = 0; it < 8; ++it) {
        int i   = it * 256 + t;          // 0..2047
        int cl  = i >> 4;                // 0..127
        int sl2 = (i & 15) * 2;          // 0,2,..,30
        float2 v = *(const float2*)&xb[(size_t)(c0 + cl) * S_IN + (s0 + sl2)];
        int q0 = __float2int_rn(v.x * 20.0f);   // round-half-even == jnp.round
        int q1 = __float2int_rn(v.y * 20.0f);
        q0 = max(-128, min(127, q0));
        q1 = max(-128, min(127, q1));
        tile[sl2 * 130 + cl]       = __int2half_rn(q0);   // exact (|q|<=128)
        tile[(sl2 + 1) * 130 + cl] = __int2half_rn(q1);
    }
    __syncthreads();

    __half* ob = g_xh + ((size_t)n * S_IN + s0) * CIN + c0;
#pragma unroll
    for (int it = 0; it < 8; ++it) {
        int u  = it * 256 + t;
        int sl = u >> 6;   // 0..31
        int cu = u & 63;   // channel pairs
        uint32_t val = *(const uint32_t*)&tile[sl * 130 + cu * 2];
        *(uint32_t*)&ob[(size_t)sl * CIN + cu * 2] = val;
    }
}

// ---------------------------------------------------------------------------
// Kernel 2: implicit GEMM conv, fp16 mma.sync m16n8k16, R6-proven 2-stage
// loop (.ca restored). NEW shape: CTA tile 128(M) x 64(N), 8 warps as
// 4(M) x 2(N), warp tile 32x32 -> acc = 32 regs/thread (was 64).
// Smem/stage = 192 rows x 144B = 27648; 2 stages = 55296 -> 4 CTAs/SM
// (221KB smem, 64-reg cap). 32 warps/SM = 2x latency hiding; 4 independent
// barrier groups. Per-SMSP tensor work per chunk unchanged.
// ---------------------------------------------------------------------------
#define PITCH 144
#define ATILE (128 * PITCH)          // A tile: 18432
#define BTILE (64 * PITCH)           // B tile: 9216
#define STGB  (ATILE + BTILE)        // 27648 per stage
#define SMEMT (2 * STGB)             // 55296 (2 stages)

__device__ __forceinline__ void cp16(uint32_t dst, const void* src, int sz) {
    asm volatile("cp.async.ca.shared.global [%0], [%1], 16, %2;\n"
                 :: "r"(dst), "l"(src), "r"(sz));
}
#define LDSM4(r0, r1, r2, r3, addr)                                          \
    asm volatile("ldmatrix.sync.aligned.m8n8.x4.shared.b16 {%0,%1,%2,%3}, [%4];" \
                 : "=r"(r0), "=r"(r1), "=r"(r2), "=r"(r3) : "r"(addr))
#define MMAF16(d, a, b0_, b1_)                                                \
    asm volatile(                                                             \
        "mma.sync.aligned.m16n8k16.row.col.f32.f16.f16.f32 "                 \
        "{%0,%1,%2,%3}, {%4,%5,%6,%7}, {%8,%9}, {%0,%1,%2,%3};\n"            \
        : "+f"(d[0]), "+f"(d[1]), "+f"(d[2]), "+f"(d[3])                     \
        : "r"(a[0]), "r"(a[1]), "r"(a[2]), "r"(a[3]), "r"(b0_), "r"(b1_))

__global__ void __launch_bounds__(256, 4) conv_mma_kernel(float* __restrict__ out) {
    extern __shared__ char dsm[];
    const uint32_t sbase = (uint32_t)__cvta_generic_to_shared(dsm);

    const int t      = threadIdx.x;
    const int lane   = t & 31;
    const int warp_m = (t >> 5) & 3;   // 0..3
    const int warp_n = t >> 7;         // 0..1
    const int m0     = blockIdx.x * 128;
    const int co0    = blockIdx.y * 64;

    // A loader: thread t -> row t/2 (0..127), 64B half t%2
    const int lrow  = t >> 1;
    const int lhalf = t & 1;

    int m   = m0 + lrow;
    int n   = m / S_OUT;
    int rem = m - n * S_OUT;
    int ho  = rem / WOUT;
    int wo  = rem - ho * WOUT;
    const int hb = 2 * ho - 1;
    const int wb = 2 * wo - 1;
    const __half* an = g_xh + (size_t)n * S_IN * CIN + lhalf * 32;
    // B loader: threads t<128 -> row t/2 (0..63), 64B half t%2
    const __half* bw = g_wh + (size_t)(co0 + lrow) * 9 * CIN + lhalf * 32;  // valid for t<128

    const uint32_t dstA = sbase + (uint32_t)(lrow * PITCH + lhalf * 64);
    const uint32_t dstB = sbase + ATILE + (uint32_t)(lrow * PITCH + lhalf * 64);

    // ldmatrix lane offsets (proven fragment maps)
    const uint32_t a_lane = (uint32_t)((lane & 15) * PITCH + (lane >> 4) * 16);
    const uint32_t b_lane = (uint32_t)(((lane & 7) + ((lane >> 4) << 3)) * PITCH +
                                       (((lane >> 3) & 1) << 4));
    const uint32_t aBase0 = sbase + (warp_m * 32) * PITCH + a_lane;
    const uint32_t bBase0 = sbase + ATILE + (warp_n * 32) * PITCH + b_lane;

    float acc[2][4][4];
#pragma unroll
    for (int mi = 0; mi < 2; ++mi)
#pragma unroll
        for (int ni = 0; ni < 4; ++ni)
#pragma unroll
            for (int k = 0; k < 4; ++k) acc[mi][ni][k] = 0.0f;

    auto issue = [&](int c, int st) {
        int tap = c >> 2;
        int kc  = (c & 3) * 64;
        int kh  = tap / 3;
        int kw  = tap - kh * 3;
        int hi  = hb + kh, wi = wb + kw;
        bool v  = ((unsigned)hi < (unsigned)HIN) && ((unsigned)wi < (unsigned)WIN);
        const __half* asrc = an + ((size_t)(hi * WIN + wi) * CIN + kc);
        uint32_t so = (uint32_t)(st * STGB);
#pragma unroll
        for (int i = 0; i < 4; ++i) {
            cp16(dstA + so + i * 16, v ? (const void*)(asrc + i * 8) : (const void*)g_xh,
                 v ? 16 : 0);
        }
        if (t < 128) {
            const __half* bsrc = bw + (tap * CIN + kc);
#pragma unroll
            for (int i = 0; i < 4; ++i) {
                cp16(dstB + so + i * 16, bsrc + i * 8, 16);
            }
        }
    };

    issue(0, 0);
    asm volatile("cp.async.commit_group;\n" ::: "memory");

#pragma unroll 1
    for (int c = 0; c < 36; ++c) {
        if (c < 35) {
            issue(c + 1, (c + 1) & 1);
            asm volatile("cp.async.commit_group;\n" ::: "memory");
            asm volatile("cp.async.wait_group 1;\n" ::: "memory");
        } else {
            asm volatile("cp.async.wait_group 0;\n" ::: "memory");
        }
        __syncthreads();

        const uint32_t so = (uint32_t)((c & 1) * STGB);
        const uint32_t aB = aBase0 + so;
        const uint32_t bB = bBase0 + so;
#pragma unroll
        for (int ks = 0; ks < 4; ++ks) {
            const uint32_t kb = ks * 32;   // 16 fp16 per k-step
            uint32_t a[2][4];
            LDSM4(a[0][0], a[0][1], a[0][2], a[0][3], aB + kb);
            LDSM4(a[1][0], a[1][1], a[1][2], a[1][3], aB + 16 * PITCH + kb);
#pragma unroll
            for (int p = 0; p < 2; ++p) {
                uint32_t b0, b1, b2, b3;
                LDSM4(b0, b1, b2, b3, bB + p * (16 * PITCH) + kb);
#pragma unroll
                for (int mi = 0; mi < 2; ++mi) {
                    MMAF16(acc[mi][2 * p],     a[mi], b0, b1);
                    MMAF16(acc[mi][2 * p + 1], a[mi], b2, b3);
                }
            }
        }
        __syncthreads();
    }

    // Epilogue: dequantize and store NCHW fp32 (acc are exact integers).
    const float sc = (float)(0.05 * 0.01);
#pragma unroll
    for (int mi = 0; mi < 2; ++mi) {
#pragma unroll
        for (int rr = 0; rr < 2; ++rr) {
            int mm = m0 + warp_m * 32 + mi * 16 + (lane >> 2) + rr * 8;
            int nn = mm / S_OUT;
            int ss = mm - nn * S_OUT;
            float* op = out + (size_t)nn * COUT * S_OUT + ss;
#pragma unroll
            for (int ni = 0; ni < 4; ++ni) {
                int co = co0 + warp_n * 32 + ni * 8 + (lane & 3) * 2;
                op[(size_t)co * S_OUT]       = acc[mi][ni][rr * 2 + 0] * sc;
                op[(size_t)(co + 1) * S_OUT] = acc[mi][ni][rr * 2 + 1] * sc;
            }
        }
    }
}

// ---------------------------------------------------------------------------
extern "C" void kernel_launch(void* const* d_in, const int* in_sizes, int n_in,
                              void* d_out, int out_size) {
    const float* x = (const float*)d_in[0];
    const float* w = (const float*)d_in[1];
    if (n_in >= 2 && in_sizes[0] != X_ELEMS) {
        const float* tmp = x; x = w; w = tmp;
    }
    float* out = (float*)d_out;

    dim3 g1(99, 2, 32);   // bx<98: activations; bx==98: weights (64 sub-blocks)
    quant_kernel<<<g1, 256>>>(x, w);

    cudaFuncSetAttribute(conv_mma_kernel,
                         cudaFuncAttributeMaxDynamicSharedMemorySize, SMEMT);
    dim3 g3(M_TOTAL / 128, COUT / 64);  // (196, 4) = 784 CTAs
    conv_mma_kernel<<<g3, 256, SMEMT>>>(out);
}

// round 16
// speedup vs baseline: 1.4343x; 1.2937x over previous
#include <cuda_runtime.h>
#include <cuda_fp16.h>
#include <cstdint>

#define XN 32
#define CIN 256
#define HIN 56
#define WIN 56
#define S_IN 3136
#define COUT 256
#define HOUT 28
#define WOUT 28
#define S_OUT 784
#define M_TOTAL 25088
#define X_ELEMS (XN * CIN * S_IN)

// Device scratch (no cudaMalloc allowed)
__device__ __align__(16) __half g_xh[(size_t)XN * S_IN * CIN];   // 51.4 MB NHWC fp16
__device__ __align__(16) __half g_wh[(size_t)COUT * 9 * CIN];    // [co][tap][ci] fp16

// ---------------------------------------------------------------------------
// Kernel 1: quantize x (round-half-even, clamp [-128,127]) as fp16 +
// NCHW -> N(S)C transpose via smem tile (128 ch x 32 spatial), float2 loads.
// Block column bx==98 quantizes the weights (merged; proven ~24us combined).
// ---------------------------------------------------------------------------
__global__ void quant_kernel(const float* __restrict__ x,
                             const float* __restrict__ w) {
    __shared__ __align__(16) __half tile[32 * 130];  // pitch 130 -> conflict-free
    const int t = threadIdx.x;

    if (blockIdx.x == 98) {
        // ---- weights: OIHW fp32 (int-valued) -> [co][tap][ci] fp16 ----
        const int wblock = blockIdx.y * 32 + blockIdx.z;   // 0..63
#pragma unroll 4
        for (int j = 0; j < 36; ++j) {
            int idx = wblock * 9216 + j * 256 + t;
            int co  = idx / (9 * CIN);
            int r   = idx - co * 9 * CIN;
            int tap = r >> 8;
            int ci  = r & 255;
            g_wh[idx] = __int2half_rn(
                __float2int_rn(w[(size_t)co * CIN * 9 + (size_t)ci * 9 + tap]));
        }
        return;
    }

    const int n  = blockIdx.z;
    const int c0 = blockIdx.y * 128;
    const int s0 = blockIdx.x * 32;

    const float* xb = x + (size_t)n * CIN * S_IN;
#pragma unroll
    for (int it = 0; it < 8; ++it) {
        int i   = it * 256 + t;          // 0..2047
        int cl  = i >> 4;                // 0..127
        int sl2 = (i & 15) * 2;          // 0,2,..,30
        float2 v = *(const float2*)&xb[(size_t)(c0 + cl) * S_IN + (s0 + sl2)];
        int q0 = __float2int_rn(v.x * 20.0f);   // round-half-even == jnp.round
        int q1 = __float2int_rn(v.y * 20.0f);
        q0 = max(-128, min(127, q0));
        q1 = max(-128, min(127, q1));
        tile[sl2 * 130 + cl]       = __int2half_rn(q0);   // exact (|q|<=128)
        tile[(sl2 + 1) * 130 + cl] = __int2half_rn(q1);
    }
    __syncthreads();

    __half* ob = g_xh + ((size_t)n * S_IN + s0) * CIN + c0;
#pragma unroll
    for (int it = 0; it < 8; ++it) {
        int u  = it * 256 + t;
        int sl = u >> 6;   // 0..31
        int cu = u & 63;   // channel pairs
        uint32_t val = *(const uint32_t*)&tile[sl * 130 + cu * 2];
        *(uint32_t*)&ob[(size_t)sl * CIN + cu * 2] = val;
    }
}

// ---------------------------------------------------------------------------
// Kernel 2: implicit GEMM conv, fp16 mma.sync m16n8k16 — EXACT R6 body
// (the proven-fastest configuration, conv ~133us): cp.async.ca, 2-stage,
// issue(c+1) -> commit -> wait 1 -> sync -> compute -> sync, occ 2 uncapped.
// CTA tile 128(M) x 128(N). 8 warps: 4(M) x 2(N), warp tile 32x64.
// K: 36 chunks = 9 taps x 4 sub-chunks of 64 channels (4 x k16 per chunk).
// ---------------------------------------------------------------------------
#define PITCH 144
#define TILEB (128 * PITCH)          // 18432 per A or B tile
#define STGB  (2 * TILEB)            // 36864 per stage
#define SMEMT (2 * STGB)             // 73728 (2 stages) -> occupancy 2

__device__ __forceinline__ void cp16(uint32_t dst, const void* src, int sz) {
    asm volatile("cp.async.ca.shared.global [%0], [%1], 16, %2;\n"
                 :: "r"(dst), "l"(src), "r"(sz));
}
#define LDSM4(r0, r1, r2, r3, addr)                                          \
    asm volatile("ldmatrix.sync.aligned.m8n8.x4.shared.b16 {%0,%1,%2,%3}, [%4];" \
                 : "=r"(r0), "=r"(r1), "=r"(r2), "=r"(r3) : "r"(addr))
#define MMAF16(d, a, b0_, b1_)                                                \
    asm volatile(                                                             \
        "mma.sync.aligned.m16n8k16.row.col.f32.f16.f16.f32 "                 \
        "{%0,%1,%2,%3}, {%4,%5,%6,%7}, {%8,%9}, {%0,%1,%2,%3};\n"            \
        : "+f"(d[0]), "+f"(d[1]), "+f"(d[2]), "+f"(d[3])                     \
        : "r"(a[0]), "r"(a[1]), "r"(a[2]), "r"(a[3]), "r"(b0_), "r"(b1_))

__global__ void __launch_bounds__(256, 2) conv_mma_kernel(float* __restrict__ out) {
    extern __shared__ char dsm[];
    const uint32_t sbase = (uint32_t)__cvta_generic_to_shared(dsm);

    const int t      = threadIdx.x;
    const int lane   = t & 31;
    const int warp_m = (t >> 5) & 3;   // 0..3
    const int warp_n = t >> 7;         // 0..1
    const int m0     = blockIdx.x * 128;
    const int co0    = blockIdx.y * 128;

    // Loader: thread t -> row t/2 (0..127), 64B half t%2 (4 x 16B segments)
    const int lrow  = t >> 1;
    const int lhalf = t & 1;

    int m   = m0 + lrow;
    int n   = m / S_OUT;
    int rem = m - n * S_OUT;
    int ho  = rem / WOUT;
    int wo  = rem - ho * WOUT;
    const int hb = 2 * ho - 1;
    const int wb = 2 * wo - 1;
    const __half* an = g_xh + (size_t)n * S_IN * CIN + lhalf * 32;
    const __half* bw = g_wh + (size_t)(co0 + lrow) * 9 * CIN + lhalf * 32;

    const uint32_t dstA = sbase + (uint32_t)(lrow * PITCH + lhalf * 64);
    const uint32_t dstB = dstA + TILEB;

    // ldmatrix lane offsets (proven fragment maps)
    const uint32_t a_lane = (uint32_t)((lane & 15) * PITCH + (lane >> 4) * 16);
    const uint32_t b_lane = (uint32_t)(((lane & 7) + ((lane >> 4) << 3)) * PITCH +
                                       (((lane >> 3) & 1) << 4));
    const uint32_t aBase0 = sbase + (warp_m * 32) * PITCH + a_lane;
    const uint32_t bBase0 = sbase + TILEB + (warp_n * 64) * PITCH + b_lane;

    float acc[2][8][4];
#pragma unroll
    for (int mi = 0; mi < 2; ++mi)
#pragma unroll
        for (int ni = 0; ni < 8; ++ni)
#pragma unroll
            for (int k = 0; k < 4; ++k) acc[mi][ni][k] = 0.0f;

    auto issue = [&](int c, int st) {
        int tap = c >> 2;
        int kc  = (c & 3) * 64;
        int kh  = tap / 3;
        int kw  = tap - kh * 3;
        int hi  = hb + kh, wi = wb + kw;
        bool v  = ((unsigned)hi < (unsigned)HIN) && ((unsigned)wi < (unsigned)WIN);
        const __half* asrc = an + ((size_t)(hi * WIN + wi) * CIN + kc);
        const __half* bsrc = bw + (tap * CIN + kc);
        uint32_t so = (uint32_t)(st * STGB);
#pragma unroll
        for (int i = 0; i < 4; ++i) {
            cp16(dstA + so + i * 16, v ? (const void*)(asrc + i * 8) : (const void*)g_xh,
                 v ? 16 : 0);
            cp16(dstB + so + i * 16, bsrc + i * 8, 16);
        }
    };

    issue(0, 0);
    asm volatile("cp.async.commit_group;\n" ::: "memory");

#pragma unroll 1
    for (int c = 0; c < 36; ++c) {
        if (c < 35) {
            issue(c + 1, (c + 1) & 1);
            asm volatile("cp.async.commit_group;\n" ::: "memory");
            asm volatile("cp.async.wait_group 1;\n" ::: "memory");
        } else {
            asm volatile("cp.async.wait_group 0;\n" ::: "memory");
        }
        __syncthreads();

        const uint32_t so = (uint32_t)((c & 1) * STGB);
        const uint32_t aB = aBase0 + so;
        const uint32_t bB = bBase0 + so;
#pragma unroll
        for (int ks = 0; ks < 4; ++ks) {
            const uint32_t kb = ks * 32;   // 16 fp16 per k-step
            uint32_t a[2][4];
            LDSM4(a[0][0], a[0][1], a[0][2], a[0][3], aB + kb);
            LDSM4(a[1][0], a[1][1], a[1][2], a[1][3], aB + 16 * PITCH + kb);
#pragma unroll
            for (int p = 0; p < 4; ++p) {
                uint32_t b0, b1, b2, b3;
                LDSM4(b0, b1, b2, b3, bB + p * (16 * PITCH) + kb);
#pragma unroll
                for (int mi = 0; mi < 2; ++mi) {
                    MMAF16(acc[mi][2 * p],     a[mi], b0, b1);
                    MMAF16(acc[mi][2 * p + 1], a[mi], b2, b3);
                }
            }
        }
        __syncthreads();
    }

    // Epilogue: dequantize and store NCHW fp32 (acc are exact integers).
    const float sc = (float)(0.05 * 0.01);
#pragma unroll
    for (int mi = 0; mi < 2; ++mi) {
#pragma unroll
        for (int rr = 0; rr < 2; ++rr) {
            int mm = m0 + warp_m * 32 + mi * 16 + (lane >> 2) + rr * 8;
            int nn = mm / S_OUT;
            int ss = mm - nn * S_OUT;
            float* op = out + (size_t)nn * COUT * S_OUT + ss;
#pragma unroll
            for (int ni = 0; ni < 8; ++ni) {
                int co = co0 + warp_n * 64 + ni * 8 + (lane & 3) * 2;
                op[(size_t)co * S_OUT]       = acc[mi][ni][rr * 2 + 0] * sc;
                op[(size_t)(co + 1) * S_OUT] = acc[mi][ni][rr * 2 + 1] * sc;
            }
        }
    }
}

// ---------------------------------------------------------------------------
extern "C" void kernel_launch(void* const* d_in, const int* in_sizes, int n_in,
                              void* d_out, int out_size) {
    const float* x = (const float*)d_in[0];
    const float* w = (const float*)d_in[1];
    if (n_in >= 2 && in_sizes[0] != X_ELEMS) {
        const float* tmp = x; x = w; w = tmp;
    }
    float* out = (float*)d_out;

    dim3 g1(99, 2, 32);   // bx<98: activations; bx==98: weights (64 sub-blocks)
    quant_kernel<<<g1, 256>>>(x, w);

    cudaFuncSetAttribute(conv_mma_kernel,
                         cudaFuncAttributeMaxDynamicSharedMemorySize, SMEMT);
    dim3 g3(M_TOTAL / 128, COUT / 128);  // (196, 2)
    conv_mma_kernel<<<g3, 256, SMEMT>>>(out);
}